// round 1
// baseline (speedup 1.0000x reference)
#include <cuda_runtime.h>
#include <cstdint>

// ---------------------------------------------------------------------------
// StackedBidirectionalLSTMEncoder  (B=64, T=256, V=128, E=512, U=512)
// Round 1: full-fp32 baseline using fma.rn.f32x2 (FFMA2) everywhere.
//   embed -> gemm(zx1 f/b) -> scan L1 (persistent, 128 CTAs, per-step barrier)
//         -> gemm(zx2 f/b) -> scan L2 (writes d_out directly)
// ---------------------------------------------------------------------------

#define kB 64
#define kT 256
#define kE 512
#define kU 512
#define kG 2048   /* 4U */
#define kF 1024   /* 2U */

// ------------------------------ scratch ------------------------------------
__device__ float g_x[kT * kB * kE];                 //  33.5 MB, time-major [t][b][e]
__device__ float g_zx0[33554432];                   // 134 MB  [t*B+b][4U]  (fwd dir)
__device__ float g_zx1[33554432];                   // 134 MB  (bwd dir)
__device__ float g_out1[16777216];                  //  67 MB  [t*B+b][2U]
__device__ float g_h[2][2][kB * kU];                // [dir][parity][b*U]
__device__ unsigned char g_mask[kT * kB];           // mask_t [t][b]
__device__ unsigned int g_bar[2];                   // per-direction barrier counter

// ------------------------------ f32x2 helpers ------------------------------
__device__ __forceinline__ unsigned long long pk2(float lo, float hi) {
    unsigned long long r;
    asm("mov.b64 %0, {%1, %2};" : "=l"(r) : "f"(lo), "f"(hi));
    return r;
}
__device__ __forceinline__ void upk2(unsigned long long v, float& lo, float& hi) {
    asm("mov.b64 {%0, %1}, %2;" : "=f"(lo), "=f"(hi) : "l"(v));
}
__device__ __forceinline__ unsigned long long ffma2(unsigned long long a,
                                                    unsigned long long b,
                                                    unsigned long long c) {
    unsigned long long d;
    asm("fma.rn.f32x2 %0, %1, %2, %3;" : "=l"(d) : "l"(a), "l"(b), "l"(c));
    return d;
}

__device__ __forceinline__ float sigmoidf_(float x) {
    return 1.0f / (1.0f + __expf(-x));
}

// ------------------------------ embed + mask --------------------------------
__global__ void embed_kernel(const int* __restrict__ enc, const float* __restrict__ emb) {
    int bid = blockIdx.x;            // 0 .. T*B-1
    int t = bid >> 6;
    int b = bid & 63;
    int idx = enc[b * kT + t];       // enc is [B,T]
    if (threadIdx.x == 0) g_mask[t * kB + b] = (idx != 0) ? 1 : 0;
    const float4* src = (const float4*)(emb + (size_t)idx * kE);
    float4* dst = (float4*)(g_x + (size_t)(t * kB + b) * kE);
    int i = threadIdx.x;             // 128 threads, 128 float4 = 512 floats
    dst[i] = src[i];
}

// ------------------------------ init (h buffers + barriers) -----------------
__global__ void init_kernel() {
    int i = blockIdx.x * blockDim.x + threadIdx.x;
    if (i < 2) g_bar[i] = 0u;
    float* h = (float*)g_h;
    for (int j = i; j < 2 * 2 * kB * kU; j += gridDim.x * blockDim.x) h[j] = 0.0f;
}

// ------------------------------ GEMM ----------------------------------------
// C[M,2048] = A[M,K] @ W[K,2048] + bias.  BM=BN=128, BK=16, 256 thr, 8x8/thread.
__global__ __launch_bounds__(256, 2) void gemm_kernel(
    int a_sel,                       // 0: g_x (K=512), 1: g_out1 (K=1024)
    const float* __restrict__ W,
    const float* __restrict__ bias,
    int c_sel,                       // 0: g_zx0, 1: g_zx1
    int K) {
    const float* __restrict__ A = a_sel ? g_out1 : g_x;
    float* __restrict__ C = c_sel ? g_zx1 : g_zx0;

    __shared__ float As[16][136];    // padded: conflict-free transposed stores
    __shared__ float Bs[16][128];

    const int tid = threadIdx.x;
    const int tx = tid & 15;
    const int ty = tid >> 4;
    const int m0 = blockIdx.y * 128;
    const int n0 = blockIdx.x * 128;

    unsigned long long acc[8][4];
#pragma unroll
    for (int i = 0; i < 8; i++)
#pragma unroll
        for (int j = 0; j < 4; j++) acc[i][j] = pk2(0.0f, 0.0f);

    for (int k0 = 0; k0 < K; k0 += 16) {
#pragma unroll
        for (int l = 0; l < 2; ++l) {
            int f = tid + l * 256;               // 0..511
            int m = f >> 2, kc = (f & 3) * 4;
            float4 v = *(const float4*)(A + (size_t)(m0 + m) * K + k0 + kc);
            As[kc + 0][m] = v.x; As[kc + 1][m] = v.y;
            As[kc + 2][m] = v.z; As[kc + 3][m] = v.w;
            int kr = f >> 5, nc = (f & 31) * 4;
            *(float4*)&Bs[kr][nc] =
                *(const float4*)(W + (size_t)(k0 + kr) * kG + n0 + nc);
        }
        __syncthreads();
#pragma unroll
        for (int k = 0; k < 16; ++k) {
            float4 a0 = *(const float4*)&As[k][ty * 8];
            float4 a1 = *(const float4*)&As[k][ty * 8 + 4];
            float4 b0 = *(const float4*)&Bs[k][tx * 8];
            float4 b1 = *(const float4*)&Bs[k][tx * 8 + 4];
            unsigned long long bp[4] = {pk2(b0.x, b0.y), pk2(b0.z, b0.w),
                                        pk2(b1.x, b1.y), pk2(b1.z, b1.w)};
            float av[8] = {a0.x, a0.y, a0.z, a0.w, a1.x, a1.y, a1.z, a1.w};
#pragma unroll
            for (int i = 0; i < 8; i++) {
                unsigned long long ad = pk2(av[i], av[i]);
#pragma unroll
                for (int j = 0; j < 4; j++) acc[i][j] = ffma2(ad, bp[j], acc[i][j]);
            }
        }
        __syncthreads();
    }
    // epilogue: + bias, vectorized stores
#pragma unroll
    for (int i = 0; i < 8; i++) {
        int m = m0 + ty * 8 + i;
#pragma unroll
        for (int jh = 0; jh < 2; jh++) {
            float l0, h0, l1, h1;
            upk2(acc[i][jh * 2 + 0], l0, h0);
            upk2(acc[i][jh * 2 + 1], l1, h1);
            int n = n0 + tx * 8 + jh * 4;
            float4 v;
            v.x = l0 + bias[n + 0];
            v.y = h0 + bias[n + 1];
            v.z = l1 + bias[n + 2];
            v.w = h1 + bias[n + 3];
            *(float4*)(C + (size_t)m * kG + n) = v;
        }
    }
}

// ------------------------------ persistent scan -----------------------------
// 128 CTAs: CTA = dir*64 + g; each owns 8 hidden units (32 gate cols).
// SMEM: Ur slice [512][32] (col = jj*4 + q), h chunk [64][260].
#define HS_STRIDE 260
#define SMEM_SCAN_BYTES ((512 * 32 + 64 * HS_STRIDE) * 4)

__global__ __launch_bounds__(256, 1) void scan_kernel(
    const float* __restrict__ Ur_f, const float* __restrict__ Ur_b,
    float* __restrict__ out2,       // layer2 only: d_out [b][t][1024]
    float* __restrict__ h_final,    // layer2 only
    float* __restrict__ c_final,    // layer2 only
    int layer2) {
    extern __shared__ float smem[];
    float* w_s = smem;                  // 512*32
    float* h_s = smem + 512 * 32;       // 64*260

    const int cta = blockIdx.x;
    const int d = cta >> 6;             // direction
    const int g = cta & 63;
    const int j0 = g * 8;
    const int tid = threadIdx.x;
    const int tc = tid & 7;             // hidden unit within slice
    const int tr = tid >> 3;            // 0..31
    const int r0 = tr, r1 = tr + 32;    // batch rows owned

    const float* __restrict__ zx = d ? g_zx1 : g_zx0;
    const float* __restrict__ Ur = d ? Ur_b : Ur_f;

    // load Ur slice once: w_s[k][jj*4+q] = Ur[k][q*512 + j0 + jj]
    for (int i = tid; i < 512 * 32; i += 256) {
        int k = i >> 5, c = i & 31;
        int q = c & 3, jj = c >> 2;
        w_s[i] = Ur[(size_t)k * kG + q * kU + j0 + jj];
    }
    __syncthreads();

    // per-thread private state (exclusively owned (b, j) cells)
    float hp0 = 0.0f, hp1 = 0.0f, cp0 = 0.0f, cp1 = 0.0f;

    for (int s = 0; s < kT; ++s) {
        const int t = d ? (kT - 1 - s) : s;
        const int pr = s & 1;
        const float* __restrict__ hin = g_h[d][pr];
        float* __restrict__ hout = g_h[d][pr ^ 1];

        // prefetch zx + mask (hidden under GEMM chunks)
        float zr0[4], zr1[4];
#pragma unroll
        for (int q = 0; q < 4; q++) {
            zr0[q] = __ldg(&zx[((size_t)t * kB + r0) * kG + q * kU + j0 + tc]);
            zr1[q] = __ldg(&zx[((size_t)t * kB + r1) * kG + q * kU + j0 + tc]);
        }
        int m0 = g_mask[t * kB + r0];
        int m1 = g_mask[t * kB + r1];

        unsigned long long a00 = pk2(0.f, 0.f), a01 = pk2(0.f, 0.f);
        unsigned long long a10 = pk2(0.f, 0.f), a11 = pk2(0.f, 0.f);

#pragma unroll
        for (int ch = 0; ch < 2; ++ch) {
            __syncthreads();
            // stage h chunk [64][256] via L2 (bypass L1 to avoid stale lines)
            for (int i = tid; i < 64 * 64; i += 256) {
                int r = i >> 6, c4 = i & 63;
                float4 v = __ldcg((const float4*)(hin + r * kU + ch * 256 + c4 * 4));
                *(float4*)&h_s[r * HS_STRIDE + c4 * 4] = v;
            }
            __syncthreads();
            const float* wp = w_s + (size_t)ch * 256 * 32;
#pragma unroll 4
            for (int k = 0; k < 256; ++k) {
                float4 w = *(const float4*)&wp[k * 32 + tc * 4];
                unsigned long long w01 = pk2(w.x, w.y);
                unsigned long long w23 = pk2(w.z, w.w);
                float h0 = h_s[r0 * HS_STRIDE + k];
                float h1 = h_s[r1 * HS_STRIDE + k];
                unsigned long long hd0 = pk2(h0, h0);
                unsigned long long hd1 = pk2(h1, h1);
                a00 = ffma2(hd0, w01, a00);
                a01 = ffma2(hd0, w23, a01);
                a10 = ffma2(hd1, w01, a10);
                a11 = ffma2(hd1, w23, a11);
            }
        }

        // ----- epilogue row r0 -----
        {
            float zi, zf, zg, zo;
            upk2(a00, zi, zf);
            upk2(a01, zg, zo);
            zi += zr0[0]; zf += zr0[1]; zg += zr0[2]; zo += zr0[3];
            float ii = sigmoidf_(zi), ff = sigmoidf_(zf);
            float gg = tanhf(zg), oo = sigmoidf_(zo);
            float cn = ff * cp0 + ii * gg;
            float hn = oo * tanhf(cn);
            if (!m0) { hn = hp0; cn = cp0; }
            hp0 = hn; cp0 = cn;
            __stcg(&hout[r0 * kU + j0 + tc], hn);
            if (!layer2) {
                g_out1[((size_t)t * kB + r0) * kF + d * kU + j0 + tc] = hn;
            } else {
                out2[((size_t)r0 * kT + t) * kF + d * kU + j0 + tc] = hn;
                if (s == kT - 1) {
                    h_final[r0 * kF + d * kU + j0 + tc] = hn;
                    c_final[r0 * kF + d * kU + j0 + tc] = cn;
                }
            }
        }
        // ----- epilogue row r1 -----
        {
            float zi, zf, zg, zo;
            upk2(a10, zi, zf);
            upk2(a11, zg, zo);
            zi += zr1[0]; zf += zr1[1]; zg += zr1[2]; zo += zr1[3];
            float ii = sigmoidf_(zi), ff = sigmoidf_(zf);
            float gg = tanhf(zg), oo = sigmoidf_(zo);
            float cn = ff * cp1 + ii * gg;
            float hn = oo * tanhf(cn);
            if (!m1) { hn = hp1; cn = cp1; }
            hp1 = hn; cp1 = cn;
            __stcg(&hout[r1 * kU + j0 + tc], hn);
            if (!layer2) {
                g_out1[((size_t)t * kB + r1) * kF + d * kU + j0 + tc] = hn;
            } else {
                out2[((size_t)r1 * kT + t) * kF + d * kU + j0 + tc] = hn;
                if (s == kT - 1) {
                    h_final[r1 * kF + d * kU + j0 + tc] = hn;
                    c_final[r1 * kF + d * kU + j0 + tc] = cn;
                }
            }
        }

        // ----- inter-CTA barrier (per direction group, monotonic counter) ----
        if (s != kT - 1) {
            __threadfence();
            __syncthreads();
            if (tid == 0) {
                unsigned tgt = 64u * (unsigned)(s + 1);
                atomicAdd(&g_bar[d], 1u);
                unsigned v;
                do {
                    asm volatile("ld.global.cg.u32 %0, [%1];"
                                 : "=r"(v) : "l"(&g_bar[d]) : "memory");
                    if (v < tgt) __nanosleep(64);
                } while (v < tgt);
                __threadfence();
            }
            __syncthreads();
        }
    }
}

// ------------------------------ launch --------------------------------------
extern "C" void kernel_launch(void* const* d_in, const int* in_sizes, int n_in,
                              void* d_out, int out_size) {
    const int*   enc = (const int*)d_in[0];
    const float* emb = (const float*)d_in[1];
    const float* W1f = (const float*)d_in[2];
    const float* U1f = (const float*)d_in[3];
    const float* b1f = (const float*)d_in[4];
    const float* W1b = (const float*)d_in[5];
    const float* U1b = (const float*)d_in[6];
    const float* b1b = (const float*)d_in[7];
    const float* W2f = (const float*)d_in[8];
    const float* U2f = (const float*)d_in[9];
    const float* b2f = (const float*)d_in[10];
    const float* W2b = (const float*)d_in[11];
    const float* U2b = (const float*)d_in[12];
    const float* b2b = (const float*)d_in[13];

    float* out  = (float*)d_out;
    float* out2 = out;                                   // [B,T,2U]
    float* h2   = out + (size_t)kB * kT * kF;            // [B,2U]
    float* c2   = h2 + (size_t)kB * kF;                  // [B,2U]

    cudaFuncSetAttribute(scan_kernel, cudaFuncAttributeMaxDynamicSharedMemorySize,
                         SMEM_SCAN_BYTES);

    dim3 ggrid(kG / 128, (kT * kB) / 128);               // 16 x 128

    embed_kernel<<<kT * kB, 128>>>(enc, emb);

    // layer 1 input projections
    gemm_kernel<<<ggrid, 256>>>(0, W1f, b1f, 0, kE);
    gemm_kernel<<<ggrid, 256>>>(0, W1b, b1b, 1, kE);

    init_kernel<<<128, 256>>>();
    scan_kernel<<<128, 256, SMEM_SCAN_BYTES>>>(U1f, U1b, nullptr, nullptr, nullptr, 0);

    // layer 2 input projections
    gemm_kernel<<<ggrid, 256>>>(1, W2f, b2f, 0, kF);
    gemm_kernel<<<ggrid, 256>>>(1, W2b, b2b, 1, kF);

    init_kernel<<<128, 256>>>();
    scan_kernel<<<128, 256, SMEM_SCAN_BYTES>>>(U2f, U2b, out2, h2, c2, 1);
}

// round 8
// speedup vs baseline: 1.3006x; 1.3006x over previous
#include <cuda_runtime.h>
#include <cuda_bf16.h>
#include <cstdint>

// ---------------------------------------------------------------------------
// StackedBidirectionalLSTMEncoder  (B=64, T=256, V=128, E=512, U=512)
// Round 7: R4 design + fix for the real bug: __device__ symbols were passed
// as kernel args FROM HOST (host shadow address, silently wrong under ATS).
// All device globals now referenced only from device code (selector ints).
//   embW = emb@W1+b1 (V=128 -> gather replaces layer-1 GEMM entirely)
//   L1 scan (FFMA2 persistent) -> writes bf16 hi/lo A operand
//   layer-2 GEMM via warp-mma bf16, 3-stage cp.async (hi/lo 3-pass)
//   L2 scan (FFMA2 persistent) -> d_out
// ---------------------------------------------------------------------------

#define kB 64
#define kT 256
#define kE 512
#define kU 512
#define kG 2048   /* 4U */
#define kF 1024   /* 2U */

// ------------------------------ scratch ------------------------------------
__device__ float g_zx0[33554432];                   // [t*B+b][2048] fwd (layer2)
__device__ float g_zx1[33554432];                   // bwd
__device__ __nv_bfloat16 g_ah[16777216];            // A hi  [16384][1024]
__device__ __nv_bfloat16 g_al[16777216];            // A lo
__device__ __nv_bfloat16 g_bh0[2097152];            // W2f^T hi [2048][1024]
__device__ __nv_bfloat16 g_bl0[2097152];
__device__ __nv_bfloat16 g_bh1[2097152];            // W2b^T hi
__device__ __nv_bfloat16 g_bl1[2097152];
__device__ float g_embw0[262144];                   // emb@W1f+b1f [128][2048]
__device__ float g_embw1[262144];
__device__ float g_h[2][2][kB * kU];                // [dir][parity][b*U]
__device__ unsigned int g_bar[2];

// ------------------------------ f32x2 helpers ------------------------------
__device__ __forceinline__ unsigned long long pk2(float lo, float hi) {
    unsigned long long r;
    asm("mov.b64 %0, {%1, %2};" : "=l"(r) : "f"(lo), "f"(hi));
    return r;
}
__device__ __forceinline__ void upk2(unsigned long long v, float& lo, float& hi) {
    asm("mov.b64 {%0, %1}, %2;" : "=f"(lo), "=f"(hi) : "l"(v));
}
__device__ __forceinline__ unsigned long long ffma2(unsigned long long a,
                                                    unsigned long long b,
                                                    unsigned long long c) {
    unsigned long long d;
    asm("fma.rn.f32x2 %0, %1, %2, %3;" : "=l"(d) : "l"(a), "l"(b), "l"(c));
    return d;
}
__device__ __forceinline__ float sigmoidf_(float x) {
    return 1.0f / (1.0f + __expf(-x));
}

// ------------------------------ cp.async helpers ----------------------------
__device__ __forceinline__ uint32_t smem_u32(const void* p) {
    uint32_t a;
    asm("{ .reg .u64 t; cvta.to.shared.u64 t, %1; cvt.u32.u64 %0, t; }"
        : "=r"(a) : "l"(p));
    return a;
}
__device__ __forceinline__ void cp16(uint32_t d, const void* s) {
    asm volatile("cp.async.cg.shared.global [%0], [%1], 16;" :: "r"(d), "l"(s));
}
__device__ __forceinline__ void cp_commit() { asm volatile("cp.async.commit_group;" ::: "memory"); }
__device__ __forceinline__ void cp_wait1()  { asm volatile("cp.async.wait_group 1;" ::: "memory"); }
__device__ __forceinline__ void cp_wait0()  { asm volatile("cp.async.wait_group 0;" ::: "memory"); }

// bf16 warp mma: D(16x8,f32) += A(16x16 row) * B(16x8 col)
__device__ __forceinline__ void mma16816(float* c, const uint32_t* a,
                                         const uint32_t* b) {
    asm volatile(
        "mma.sync.aligned.m16n8k16.row.col.f32.bf16.bf16.f32 "
        "{%0,%1,%2,%3}, {%4,%5,%6,%7}, {%8,%9}, {%0,%1,%2,%3};"
        : "+f"(c[0]), "+f"(c[1]), "+f"(c[2]), "+f"(c[3])
        : "r"(a[0]), "r"(a[1]), "r"(a[2]), "r"(a[3]), "r"(b[0]), "r"(b[1]));
}

// ------------------------------ init ----------------------------------------
__global__ void init_kernel() {
    int i = blockIdx.x * blockDim.x + threadIdx.x;
    if (i < 2) g_bar[i] = 0u;
    float* h = (float*)g_h;
    for (int j = i; j < 2 * 2 * kB * kU; j += gridDim.x * blockDim.x) h[j] = 0.0f;
}

// ------------------------------ fp32 GEMM (embW only; M=128) ---------------
// C selected IN DEVICE CODE (c_sel) — never pass __device__ symbols from host.
__global__ __launch_bounds__(256, 2) void gemm_f32(
    const float* __restrict__ A, const float* __restrict__ W,
    const float* __restrict__ bias, int c_sel, int K) {
    float* __restrict__ C = c_sel ? g_embw1 : g_embw0;
    __shared__ float As[16][136];
    __shared__ float Bs[16][128];
    const int tid = threadIdx.x;
    const int tx = tid & 15;
    const int ty = tid >> 4;
    const int m0 = blockIdx.y * 128;
    const int n0 = blockIdx.x * 128;

    unsigned long long acc[8][4];
#pragma unroll
    for (int i = 0; i < 8; i++)
#pragma unroll
        for (int j = 0; j < 4; j++) acc[i][j] = pk2(0.0f, 0.0f);

    for (int k0 = 0; k0 < K; k0 += 16) {
#pragma unroll
        for (int l = 0; l < 2; ++l) {
            int f = tid + l * 256;
            int m = f >> 2, kc = (f & 3) * 4;
            float4 v = *(const float4*)(A + (size_t)(m0 + m) * K + k0 + kc);
            As[kc + 0][m] = v.x; As[kc + 1][m] = v.y;
            As[kc + 2][m] = v.z; As[kc + 3][m] = v.w;
            int kr = f >> 5, nc = (f & 31) * 4;
            *(float4*)&Bs[kr][nc] =
                *(const float4*)(W + (size_t)(k0 + kr) * kG + n0 + nc);
        }
        __syncthreads();
#pragma unroll
        for (int k = 0; k < 16; ++k) {
            float4 a0 = *(const float4*)&As[k][ty * 8];
            float4 a1 = *(const float4*)&As[k][ty * 8 + 4];
            float4 b0 = *(const float4*)&Bs[k][tx * 8];
            float4 b1 = *(const float4*)&Bs[k][tx * 8 + 4];
            unsigned long long bp[4] = {pk2(b0.x, b0.y), pk2(b0.z, b0.w),
                                        pk2(b1.x, b1.y), pk2(b1.z, b1.w)};
            float av[8] = {a0.x, a0.y, a0.z, a0.w, a1.x, a1.y, a1.z, a1.w};
#pragma unroll
            for (int i = 0; i < 8; i++) {
                unsigned long long ad = pk2(av[i], av[i]);
#pragma unroll
                for (int j = 0; j < 4; j++) acc[i][j] = ffma2(ad, bp[j], acc[i][j]);
            }
        }
        __syncthreads();
    }
#pragma unroll
    for (int i = 0; i < 8; i++) {
        int m = m0 + ty * 8 + i;
#pragma unroll
        for (int jh = 0; jh < 2; jh++) {
            float l0, h0, l1, h1;
            upk2(acc[i][jh * 2 + 0], l0, h0);
            upk2(acc[i][jh * 2 + 1], l1, h1);
            int n = n0 + tx * 8 + jh * 4;
            float4 v;
            v.x = l0 + bias[n + 0];
            v.y = h0 + bias[n + 1];
            v.z = l1 + bias[n + 2];
            v.w = h1 + bias[n + 3];
            *(float4*)(C + (size_t)m * kG + n) = v;
        }
    }
}

// ------------------------------ W2 transpose + bf16 split -------------------
// W [1024,2048] fp32 -> Bt_hi/lo [2048][1024] bf16 (Bt[n][k] = W[k][n])
__global__ void wsplit_kernel(const float* __restrict__ W2f,
                              const float* __restrict__ W2b) {
    __shared__ float s[32][33];
    const int d = blockIdx.z;
    const float* __restrict__ W = d ? W2b : W2f;
    __nv_bfloat16* __restrict__ Bh = d ? g_bh1 : g_bh0;
    __nv_bfloat16* __restrict__ Bl = d ? g_bl1 : g_bl0;
    const int n0 = blockIdx.x * 32, k0 = blockIdx.y * 32;
    const int tx = threadIdx.x & 31, ty = threadIdx.x >> 5;  // ty: 0..7
#pragma unroll
    for (int i = 0; i < 4; ++i) {
        int k = ty + i * 8;
        s[k][tx] = W[(size_t)(k0 + k) * kG + n0 + tx];
    }
    __syncthreads();
#pragma unroll
    for (int i = 0; i < 4; ++i) {
        int r = ty + i * 8;                 // local n
        float v = s[tx][r];                 // = W[k0+tx][n0+r]
        __nv_bfloat16 hi = __float2bfloat16(v);
        float lo = v - __bfloat162float(hi);
        size_t o = (size_t)(n0 + r) * 1024 + k0 + tx;
        Bh[o] = hi;
        Bl[o] = __float2bfloat16(lo);
    }
}

// ------------------------------ warp-mma layer-2 GEMM -----------------------
// zx[d][M=16384, N=2048] = A(hi+lo) @ Bt(hi+lo)^T + bias, 3-pass split.
// Tile 128x128, BK=32, 3-stage cp.async. 8 warps = 4(M) x 2(N); warp 32x64.
// SMEM per stage: Ah,Al,Bh,Bl each 128 rows x 40 bf16 (80 B stride) = 10240 B.
#define TILE_B   10240
#define STAGE_B  (4 * TILE_B)
#define MM_SMEM  (3 * STAGE_B)

__global__ __launch_bounds__(256, 1) void mma_gemm_kernel(
    const float* __restrict__ bias_f, const float* __restrict__ bias_b) {
    extern __shared__ char dynsmem[];
    const int tid = threadIdx.x;
    const int wid = tid >> 5, lane = tid & 31;
    const int g = lane >> 2, t = lane & 3;
    const int wm = wid & 3, wn = wid >> 2;
    const int d = blockIdx.z;
    const int n0 = blockIdx.x * 128;
    const int m0 = blockIdx.y * 128;
    const __nv_bfloat16* __restrict__ Bh = d ? g_bh1 : g_bh0;
    const __nv_bfloat16* __restrict__ Bl = d ? g_bl1 : g_bl0;
    const float* __restrict__ bias = d ? bias_b : bias_f;
    float* __restrict__ zx = d ? g_zx1 : g_zx0;

    const uint32_t sb32 = smem_u32(dynsmem);

    float acc[2][8][4];
#pragma unroll
    for (int mi = 0; mi < 2; mi++)
#pragma unroll
        for (int ni = 0; ni < 8; ni++)
#pragma unroll
            for (int v = 0; v < 4; v++) acc[mi][ni][v] = 0.0f;

    // load one BK=32 chunk into stage s (tiles: Ah 0, Al 1, Bh 2, Bl 3)
    auto load_chunk = [&](int s, int kc) {
        const uint32_t base = sb32 + (uint32_t)s * STAGE_B;
        const int k0 = kc * 32;
        for (int idx = tid; idx < 2048; idx += 256) {
            int tile = idx >> 9;             // 0..3
            int r = (idx >> 2) & 127;
            int c = idx & 3;
            const __nv_bfloat16* src;
            if (tile < 2) src = (tile == 0 ? g_ah : g_al) + (size_t)(m0 + r) * 1024 + k0 + c * 8;
            else          src = (tile == 2 ? Bh : Bl)     + (size_t)(n0 + r) * 1024 + k0 + c * 8;
            cp16(base + tile * TILE_B + r * 80 + c * 16, src);
        }
        cp_commit();
    };

    load_chunk(0, 0);
    load_chunk(1, 1);

    for (int c = 0; c < 32; ++c) {
        if (c + 1 < 32) cp_wait1(); else cp_wait0();
        __syncthreads();
        if (c + 2 < 32) load_chunk((c + 2) % 3, c + 2);

        const char* stg = dynsmem + (size_t)(c % 3) * STAGE_B;
        const char* pAh = stg;
        const char* pAl = stg + TILE_B;
        const char* pBh = stg + 2 * TILE_B;
        const char* pBl = stg + 3 * TILE_B;

#pragma unroll
        for (int ks = 0; ks < 2; ++ks) {
            const int kb = ks * 16;
            uint32_t ah[2][4], al[2][4];
#pragma unroll
            for (int mi = 0; mi < 2; mi++) {
                int ra = wm * 32 + mi * 16 + g;
                int co = (kb + t * 2) * 2;
                ah[mi][0] = *(const uint32_t*)(pAh + (ra)     * 80 + co);
                ah[mi][1] = *(const uint32_t*)(pAh + (ra + 8) * 80 + co);
                ah[mi][2] = *(const uint32_t*)(pAh + (ra)     * 80 + co + 16);
                ah[mi][3] = *(const uint32_t*)(pAh + (ra + 8) * 80 + co + 16);
                al[mi][0] = *(const uint32_t*)(pAl + (ra)     * 80 + co);
                al[mi][1] = *(const uint32_t*)(pAl + (ra + 8) * 80 + co);
                al[mi][2] = *(const uint32_t*)(pAl + (ra)     * 80 + co + 16);
                al[mi][3] = *(const uint32_t*)(pAl + (ra + 8) * 80 + co + 16);
            }
#pragma unroll
            for (int ni = 0; ni < 8; ni++) {
                int rb = wn * 64 + ni * 8 + g;
                int co = (kb + t * 2) * 2;
                uint32_t bh[2], bl[2];
                bh[0] = *(const uint32_t*)(pBh + rb * 80 + co);
                bh[1] = *(const uint32_t*)(pBh + rb * 80 + co + 16);
                bl[0] = *(const uint32_t*)(pBl + rb * 80 + co);
                bl[1] = *(const uint32_t*)(pBl + rb * 80 + co + 16);
#pragma unroll
                for (int mi = 0; mi < 2; mi++) {
                    mma16816(acc[mi][ni], ah[mi], bh);
                    mma16816(acc[mi][ni], al[mi], bh);
                    mma16816(acc[mi][ni], ah[mi], bl);
                }
            }
        }
        __syncthreads();
    }

    // epilogue: + bias, float2 stores
#pragma unroll
    for (int mi = 0; mi < 2; mi++) {
        int m = m0 + wm * 32 + mi * 16 + g;
#pragma unroll
        for (int ni = 0; ni < 8; ni++) {
            int n = n0 + wn * 64 + ni * 8 + t * 2;
            float bx = __ldg(bias + n), by = __ldg(bias + n + 1);
            float2 v0 = {acc[mi][ni][0] + bx, acc[mi][ni][1] + by};
            float2 v1 = {acc[mi][ni][2] + bx, acc[mi][ni][3] + by};
            *(float2*)(zx + (size_t)m * kG + n) = v0;
            *(float2*)(zx + (size_t)(m + 8) * kG + n) = v1;
        }
    }
}

// ------------------------------ persistent scan -----------------------------
// 128 CTAs: CTA = dir*64 + g; each owns 8 hidden units (32 gate cols).
#define HS_STRIDE 260
#define SMEM_SCAN_BYTES ((512 * 32 + 64 * HS_STRIDE) * 4)

__global__ __launch_bounds__(256, 1) void scan_kernel(
    const float* __restrict__ Ur_f, const float* __restrict__ Ur_b,
    const int* __restrict__ enc,
    float* __restrict__ out2, float* __restrict__ h_final,
    float* __restrict__ c_final, int layer2) {
    extern __shared__ char dynsmem[];
    float* w_s = (float*)dynsmem;                  // 512*32
    float* h_s = (float*)dynsmem + 512 * 32;       // 64*260

    const int cta = blockIdx.x;
    const int d = cta >> 6;
    const int g = cta & 63;
    const int j0 = g * 8;
    const int tid = threadIdx.x;
    const int tc = tid & 7;
    const int tr = tid >> 3;
    const int r0 = tr, r1 = tr + 32;

    const float* __restrict__ zx = d ? g_zx1 : g_zx0;
    const float* __restrict__ ew = d ? g_embw1 : g_embw0;
    const float* __restrict__ Ur = d ? Ur_b : Ur_f;

    for (int i = tid; i < 512 * 32; i += 256) {
        int k = i >> 5, c = i & 31;
        int q = c & 3, jj = c >> 2;
        w_s[i] = Ur[(size_t)k * kG + q * kU + j0 + jj];
    }
    __syncthreads();

    float hp0 = 0.0f, hp1 = 0.0f, cp0 = 0.0f, cp1 = 0.0f;

    for (int s = 0; s < kT; ++s) {
        const int t = d ? (kT - 1 - s) : s;
        const int pr = s & 1;
        const float* __restrict__ hin = g_h[d][pr];
        float* __restrict__ hout = g_h[d][pr ^ 1];

        const int tok0 = __ldg(enc + r0 * kT + t);
        const int tok1 = __ldg(enc + r1 * kT + t);
        const int m0 = tok0 != 0;
        const int m1 = tok1 != 0;

        float zr0[4], zr1[4];
        if (!layer2) {
#pragma unroll
            for (int q = 0; q < 4; q++) {
                zr0[q] = __ldg(ew + (size_t)tok0 * kG + q * kU + j0 + tc);
                zr1[q] = __ldg(ew + (size_t)tok1 * kG + q * kU + j0 + tc);
            }
        } else {
#pragma unroll
            for (int q = 0; q < 4; q++) {
                zr0[q] = __ldg(&zx[((size_t)t * kB + r0) * kG + q * kU + j0 + tc]);
                zr1[q] = __ldg(&zx[((size_t)t * kB + r1) * kG + q * kU + j0 + tc]);
            }
        }

        unsigned long long a00 = pk2(0.f, 0.f), a01 = pk2(0.f, 0.f);
        unsigned long long a10 = pk2(0.f, 0.f), a11 = pk2(0.f, 0.f);

#pragma unroll
        for (int ch = 0; ch < 2; ++ch) {
            __syncthreads();
            for (int i = tid; i < 64 * 64; i += 256) {
                int r = i >> 6, c4 = i & 63;
                float4 v = __ldcg((const float4*)(hin + r * kU + ch * 256 + c4 * 4));
                *(float4*)&h_s[r * HS_STRIDE + c4 * 4] = v;
            }
            __syncthreads();
            const float* wp = w_s + (size_t)ch * 256 * 32;
#pragma unroll 4
            for (int k = 0; k < 256; ++k) {
                float4 w = *(const float4*)&wp[k * 32 + tc * 4];
                unsigned long long w01 = pk2(w.x, w.y);
                unsigned long long w23 = pk2(w.z, w.w);
                float h0 = h_s[r0 * HS_STRIDE + k];
                float h1 = h_s[r1 * HS_STRIDE + k];
                unsigned long long hd0 = pk2(h0, h0);
                unsigned long long hd1 = pk2(h1, h1);
                a00 = ffma2(hd0, w01, a00);
                a01 = ffma2(hd0, w23, a01);
                a10 = ffma2(hd1, w01, a10);
                a11 = ffma2(hd1, w23, a11);
            }
        }

        // ----- epilogue row r0 -----
        {
            float zi, zf, zg, zo;
            upk2(a00, zi, zf);
            upk2(a01, zg, zo);
            zi += zr0[0]; zf += zr0[1]; zg += zr0[2]; zo += zr0[3];
            float ii = sigmoidf_(zi), ff = sigmoidf_(zf);
            float gg = tanhf(zg), oo = sigmoidf_(zo);
            float cn = ff * cp0 + ii * gg;
            float hn = oo * tanhf(cn);
            if (!m0) { hn = hp0; cn = cp0; }
            hp0 = hn; cp0 = cn;
            __stcg(&hout[r0 * kU + j0 + tc], hn);
            if (!layer2) {
                size_t idx = ((size_t)t * kB + r0) * kF + d * kU + j0 + tc;
                __nv_bfloat16 hi = __float2bfloat16(hn);
                g_ah[idx] = hi;
                g_al[idx] = __float2bfloat16(hn - __bfloat162float(hi));
            } else {
                out2[((size_t)r0 * kT + t) * kF + d * kU + j0 + tc] = hn;
                if (s == kT - 1) {
                    h_final[r0 * kF + d * kU + j0 + tc] = hn;
                    c_final[r0 * kF + d * kU + j0 + tc] = cn;
                }
            }
        }
        // ----- epilogue row r1 -----
        {
            float zi, zf, zg, zo;
            upk2(a10, zi, zf);
            upk2(a11, zg, zo);
            zi += zr1[0]; zf += zr1[1]; zg += zr1[2]; zo += zr1[3];
            float ii = sigmoidf_(zi), ff = sigmoidf_(zf);
            float gg = tanhf(zg), oo = sigmoidf_(zo);
            float cn = ff * cp1 + ii * gg;
            float hn = oo * tanhf(cn);
            if (!m1) { hn = hp1; cn = cp1; }
            hp1 = hn; cp1 = cn;
            __stcg(&hout[r1 * kU + j0 + tc], hn);
            if (!layer2) {
                size_t idx = ((size_t)t * kB + r1) * kF + d * kU + j0 + tc;
                __nv_bfloat16 hi = __float2bfloat16(hn);
                g_ah[idx] = hi;
                g_al[idx] = __float2bfloat16(hn - __bfloat162float(hi));
            } else {
                out2[((size_t)r1 * kT + t) * kF + d * kU + j0 + tc] = hn;
                if (s == kT - 1) {
                    h_final[r1 * kF + d * kU + j0 + tc] = hn;
                    c_final[r1 * kF + d * kU + j0 + tc] = cn;
                }
            }
        }

        // ----- inter-CTA barrier -----
        if (s != kT - 1) {
            __threadfence();
            __syncthreads();
            if (tid == 0) {
                unsigned tgt = 64u * (unsigned)(s + 1);
                atomicAdd(&g_bar[d], 1u);
                unsigned v;
                do {
                    asm volatile("ld.global.cg.u32 %0, [%1];"
                                 : "=r"(v) : "l"(&g_bar[d]) : "memory");
                    if (v < tgt) __nanosleep(64);
                } while (v < tgt);
                __threadfence();
            }
            __syncthreads();
        }
    }
}

// ------------------------------ launch --------------------------------------
extern "C" void kernel_launch(void* const* d_in, const int* in_sizes, int n_in,
                              void* d_out, int out_size) {
    const int*   enc = (const int*)d_in[0];
    const float* emb = (const float*)d_in[1];
    const float* W1f = (const float*)d_in[2];
    const float* U1f = (const float*)d_in[3];
    const float* b1f = (const float*)d_in[4];
    const float* W1b = (const float*)d_in[5];
    const float* U1b = (const float*)d_in[6];
    const float* b1b = (const float*)d_in[7];
    const float* W2f = (const float*)d_in[8];
    const float* U2f = (const float*)d_in[9];
    const float* b2f = (const float*)d_in[10];
    const float* W2b = (const float*)d_in[11];
    const float* U2b = (const float*)d_in[12];
    const float* b2b = (const float*)d_in[13];

    float* out  = (float*)d_out;
    float* out2 = out;                                   // [B,T,2U]
    float* h2   = out + (size_t)kB * kT * kF;
    float* c2   = h2 + (size_t)kB * kF;

    cudaFuncSetAttribute(scan_kernel, cudaFuncAttributeMaxDynamicSharedMemorySize,
                         SMEM_SCAN_BYTES);
    cudaFuncSetAttribute(mma_gemm_kernel, cudaFuncAttributeMaxDynamicSharedMemorySize,
                         MM_SMEM);

    // embW = emb @ W1 + b1  (V=128 -> gather replaces layer-1 GEMM)
    gemm_f32<<<dim3(16, 1), 256>>>(emb, W1f, b1f, 0, kE);
    gemm_f32<<<dim3(16, 1), 256>>>(emb, W1b, b1b, 1, kE);

    // W2 transpose + bf16 hi/lo split
    wsplit_kernel<<<dim3(64, 32, 2), 256>>>(W2f, W2b);

    // layer-1 scan (gathers zx from embW; emits bf16 hi/lo A operand)
    init_kernel<<<128, 256>>>();
    scan_kernel<<<128, 256, SMEM_SCAN_BYTES>>>(U1f, U1b, enc,
                                               nullptr, nullptr, nullptr, 0);

    // layer-2 input projection: warp-mma bf16, 3-pass split, cp.async pipeline
    mma_gemm_kernel<<<dim3(16, 128, 2), 256, MM_SMEM>>>(b2f, b2b);

    // layer-2 scan -> outputs
    init_kernel<<<128, 256>>>();
    scan_kernel<<<128, 256, SMEM_SCAN_BYTES>>>(U2f, U2b, enc,
                                               out2, h2, c2, 1);
}

// round 9
// speedup vs baseline: 1.9994x; 1.5373x over previous
#include <cuda_runtime.h>
#include <cuda_bf16.h>
#include <cstdint>

// ---------------------------------------------------------------------------
// StackedBidirectionalLSTMEncoder  (B=64, T=256, V=128, E=512, U=512)
// Round 9: recurrent scans moved to warp-mma bf16 (hi/lo 3-pass), reusing the
// fragment mapping validated by the passing mma_gemm_kernel.
//   embW = emb@W1+b1 (gather replaces layer-1 GEMM)
//   scan: persistent 128 CTAs, per-step h[64,512]@Ur[512,2048] on HMMA
//   layer-2 GEMM via warp-mma bf16 (unchanged, validated)
// ---------------------------------------------------------------------------

#define kB 64
#define kT 256
#define kE 512
#define kU 512
#define kG 2048   /* 4U */
#define kF 1024   /* 2U */

// ------------------------------ scratch ------------------------------------
__device__ float g_zx0[33554432];                   // [t*B+b][2048] fwd (layer2)
__device__ float g_zx1[33554432];                   // bwd
__device__ __nv_bfloat16 g_ah[16777216];            // A hi  [16384][1024]
__device__ __nv_bfloat16 g_al[16777216];            // A lo
__device__ __nv_bfloat16 g_bh0[2097152];            // W2f^T hi [2048][1024]
__device__ __nv_bfloat16 g_bl0[2097152];
__device__ __nv_bfloat16 g_bh1[2097152];            // W2b^T hi
__device__ __nv_bfloat16 g_bl1[2097152];
__device__ float g_embw0[262144];                   // emb@W1f+b1f [128][2048]
__device__ float g_embw1[262144];
__device__ uint32_t g_hc[2][2][2][kB * kU];         // [layer][dir][par] hi|lo<<16
__device__ unsigned int g_bar[4];                   // [layer*2+dir]

// ------------------------------ f32x2 helpers ------------------------------
__device__ __forceinline__ unsigned long long pk2(float lo, float hi) {
    unsigned long long r;
    asm("mov.b64 %0, {%1, %2};" : "=l"(r) : "f"(lo), "f"(hi));
    return r;
}
__device__ __forceinline__ void upk2(unsigned long long v, float& lo, float& hi) {
    asm("mov.b64 {%0, %1}, %2;" : "=f"(lo), "=f"(hi) : "l"(v));
}
__device__ __forceinline__ unsigned long long ffma2(unsigned long long a,
                                                    unsigned long long b,
                                                    unsigned long long c) {
    unsigned long long d;
    asm("fma.rn.f32x2 %0, %1, %2, %3;" : "=l"(d) : "l"(a), "l"(b), "l"(c));
    return d;
}
__device__ __forceinline__ float sigmoidf_(float x) {
    return 1.0f / (1.0f + __expf(-x));
}

// ------------------------------ cp.async helpers ----------------------------
__device__ __forceinline__ uint32_t smem_u32(const void* p) {
    uint32_t a;
    asm("{ .reg .u64 t; cvta.to.shared.u64 t, %1; cvt.u32.u64 %0, t; }"
        : "=r"(a) : "l"(p));
    return a;
}
__device__ __forceinline__ void cp16(uint32_t d, const void* s) {
    asm volatile("cp.async.cg.shared.global [%0], [%1], 16;" :: "r"(d), "l"(s));
}
__device__ __forceinline__ void cp_commit() { asm volatile("cp.async.commit_group;" ::: "memory"); }
__device__ __forceinline__ void cp_wait1()  { asm volatile("cp.async.wait_group 1;" ::: "memory"); }
__device__ __forceinline__ void cp_wait0()  { asm volatile("cp.async.wait_group 0;" ::: "memory"); }

// bf16 warp mma: D(16x8,f32) += A(16x16 row) * B(16x8 col)
__device__ __forceinline__ void mma16816(float* c, const uint32_t* a,
                                         const uint32_t* b) {
    asm volatile(
        "mma.sync.aligned.m16n8k16.row.col.f32.bf16.bf16.f32 "
        "{%0,%1,%2,%3}, {%4,%5,%6,%7}, {%8,%9}, {%0,%1,%2,%3};"
        : "+f"(c[0]), "+f"(c[1]), "+f"(c[2]), "+f"(c[3])
        : "r"(a[0]), "r"(a[1]), "r"(a[2]), "r"(a[3]), "r"(b[0]), "r"(b[1]));
}

// ------------------------------ init ----------------------------------------
__global__ void init_kernel() {
    int i = blockIdx.x * blockDim.x + threadIdx.x;
    if (i < 4) g_bar[i] = 0u;
    uint32_t* h = (uint32_t*)g_hc;
    for (int j = i; j < 2 * 2 * 2 * kB * kU; j += gridDim.x * blockDim.x) h[j] = 0u;
}

// ------------------------------ fp32 GEMM (embW only; M=128) ---------------
// C selected IN DEVICE CODE — never pass __device__ symbols from host.
__global__ __launch_bounds__(256, 2) void gemm_f32(
    const float* __restrict__ A, const float* __restrict__ W,
    const float* __restrict__ bias, int c_sel, int K) {
    float* __restrict__ C = c_sel ? g_embw1 : g_embw0;
    __shared__ float As[16][136];
    __shared__ float Bs[16][128];
    const int tid = threadIdx.x;
    const int tx = tid & 15;
    const int ty = tid >> 4;
    const int m0 = blockIdx.y * 128;
    const int n0 = blockIdx.x * 128;

    unsigned long long acc[8][4];
#pragma unroll
    for (int i = 0; i < 8; i++)
#pragma unroll
        for (int j = 0; j < 4; j++) acc[i][j] = pk2(0.0f, 0.0f);

    for (int k0 = 0; k0 < K; k0 += 16) {
#pragma unroll
        for (int l = 0; l < 2; ++l) {
            int f = tid + l * 256;
            int m = f >> 2, kc = (f & 3) * 4;
            float4 v = *(const float4*)(A + (size_t)(m0 + m) * K + k0 + kc);
            As[kc + 0][m] = v.x; As[kc + 1][m] = v.y;
            As[kc + 2][m] = v.z; As[kc + 3][m] = v.w;
            int kr = f >> 5, nc = (f & 31) * 4;
            *(float4*)&Bs[kr][nc] =
                *(const float4*)(W + (size_t)(k0 + kr) * kG + n0 + nc);
        }
        __syncthreads();
#pragma unroll
        for (int k = 0; k < 16; ++k) {
            float4 a0 = *(const float4*)&As[k][ty * 8];
            float4 a1 = *(const float4*)&As[k][ty * 8 + 4];
            float4 b0 = *(const float4*)&Bs[k][tx * 8];
            float4 b1 = *(const float4*)&Bs[k][tx * 8 + 4];
            unsigned long long bp[4] = {pk2(b0.x, b0.y), pk2(b0.z, b0.w),
                                        pk2(b1.x, b1.y), pk2(b1.z, b1.w)};
            float av[8] = {a0.x, a0.y, a0.z, a0.w, a1.x, a1.y, a1.z, a1.w};
#pragma unroll
            for (int i = 0; i < 8; i++) {
                unsigned long long ad = pk2(av[i], av[i]);
#pragma unroll
                for (int j = 0; j < 4; j++) acc[i][j] = ffma2(ad, bp[j], acc[i][j]);
            }
        }
        __syncthreads();
    }
#pragma unroll
    for (int i = 0; i < 8; i++) {
        int m = m0 + ty * 8 + i;
#pragma unroll
        for (int jh = 0; jh < 2; jh++) {
            float l0, h0, l1, h1;
            upk2(acc[i][jh * 2 + 0], l0, h0);
            upk2(acc[i][jh * 2 + 1], l1, h1);
            int n = n0 + tx * 8 + jh * 4;
            float4 v;
            v.x = l0 + bias[n + 0];
            v.y = h0 + bias[n + 1];
            v.z = l1 + bias[n + 2];
            v.w = h1 + bias[n + 3];
            *(float4*)(C + (size_t)m * kG + n) = v;
        }
    }
}

// ------------------------------ W2 transpose + bf16 split -------------------
__global__ void wsplit_kernel(const float* __restrict__ W2f,
                              const float* __restrict__ W2b) {
    __shared__ float s[32][33];
    const int d = blockIdx.z;
    const float* __restrict__ W = d ? W2b : W2f;
    __nv_bfloat16* __restrict__ Bh = d ? g_bh1 : g_bh0;
    __nv_bfloat16* __restrict__ Bl = d ? g_bl1 : g_bl0;
    const int n0 = blockIdx.x * 32, k0 = blockIdx.y * 32;
    const int tx = threadIdx.x & 31, ty = threadIdx.x >> 5;
#pragma unroll
    for (int i = 0; i < 4; ++i) {
        int k = ty + i * 8;
        s[k][tx] = W[(size_t)(k0 + k) * kG + n0 + tx];
    }
    __syncthreads();
#pragma unroll
    for (int i = 0; i < 4; ++i) {
        int r = ty + i * 8;
        float v = s[tx][r];
        __nv_bfloat16 hi = __float2bfloat16(v);
        float lo = v - __bfloat162float(hi);
        size_t o = (size_t)(n0 + r) * 1024 + k0 + tx;
        Bh[o] = hi;
        Bl[o] = __float2bfloat16(lo);
    }
}

// ------------------------------ warp-mma layer-2 GEMM (validated) ----------
#define TILE_B   10240
#define STAGE_B  (4 * TILE_B)
#define MM_SMEM  (3 * STAGE_B)

__global__ __launch_bounds__(256, 1) void mma_gemm_kernel(
    const float* __restrict__ bias_f, const float* __restrict__ bias_b) {
    extern __shared__ char dynsmem[];
    const int tid = threadIdx.x;
    const int wid = tid >> 5, lane = tid & 31;
    const int g = lane >> 2, t = lane & 3;
    const int wm = wid & 3, wn = wid >> 2;
    const int d = blockIdx.z;
    const int n0 = blockIdx.x * 128;
    const int m0 = blockIdx.y * 128;
    const __nv_bfloat16* __restrict__ Bh = d ? g_bh1 : g_bh0;
    const __nv_bfloat16* __restrict__ Bl = d ? g_bl1 : g_bl0;
    const float* __restrict__ bias = d ? bias_b : bias_f;
    float* __restrict__ zx = d ? g_zx1 : g_zx0;

    const uint32_t sb32 = smem_u32(dynsmem);

    float acc[2][8][4];
#pragma unroll
    for (int mi = 0; mi < 2; mi++)
#pragma unroll
        for (int ni = 0; ni < 8; ni++)
#pragma unroll
            for (int v = 0; v < 4; v++) acc[mi][ni][v] = 0.0f;

    auto load_chunk = [&](int s, int kc) {
        const uint32_t base = sb32 + (uint32_t)s * STAGE_B;
        const int k0 = kc * 32;
        for (int idx = tid; idx < 2048; idx += 256) {
            int tile = idx >> 9;
            int r = (idx >> 2) & 127;
            int c = idx & 3;
            const __nv_bfloat16* src;
            if (tile < 2) src = (tile == 0 ? g_ah : g_al) + (size_t)(m0 + r) * 1024 + k0 + c * 8;
            else          src = (tile == 2 ? Bh : Bl)     + (size_t)(n0 + r) * 1024 + k0 + c * 8;
            cp16(base + tile * TILE_B + r * 80 + c * 16, src);
        }
        cp_commit();
    };

    load_chunk(0, 0);
    load_chunk(1, 1);

    for (int c = 0; c < 32; ++c) {
        if (c + 1 < 32) cp_wait1(); else cp_wait0();
        __syncthreads();
        if (c + 2 < 32) load_chunk((c + 2) % 3, c + 2);

        const char* stg = dynsmem + (size_t)(c % 3) * STAGE_B;
        const char* pAh = stg;
        const char* pAl = stg + TILE_B;
        const char* pBh = stg + 2 * TILE_B;
        const char* pBl = stg + 3 * TILE_B;

#pragma unroll
        for (int ks = 0; ks < 2; ++ks) {
            const int kb = ks * 16;
            uint32_t ah[2][4], al[2][4];
#pragma unroll
            for (int mi = 0; mi < 2; mi++) {
                int ra = wm * 32 + mi * 16 + g;
                int co = (kb + t * 2) * 2;
                ah[mi][0] = *(const uint32_t*)(pAh + (ra)     * 80 + co);
                ah[mi][1] = *(const uint32_t*)(pAh + (ra + 8) * 80 + co);
                ah[mi][2] = *(const uint32_t*)(pAh + (ra)     * 80 + co + 16);
                ah[mi][3] = *(const uint32_t*)(pAh + (ra + 8) * 80 + co + 16);
                al[mi][0] = *(const uint32_t*)(pAl + (ra)     * 80 + co);
                al[mi][1] = *(const uint32_t*)(pAl + (ra + 8) * 80 + co);
                al[mi][2] = *(const uint32_t*)(pAl + (ra)     * 80 + co + 16);
                al[mi][3] = *(const uint32_t*)(pAl + (ra + 8) * 80 + co + 16);
            }
#pragma unroll
            for (int ni = 0; ni < 8; ni++) {
                int rb = wn * 64 + ni * 8 + g;
                int co = (kb + t * 2) * 2;
                uint32_t bh[2], bl[2];
                bh[0] = *(const uint32_t*)(pBh + rb * 80 + co);
                bh[1] = *(const uint32_t*)(pBh + rb * 80 + co + 16);
                bl[0] = *(const uint32_t*)(pBl + rb * 80 + co);
                bl[1] = *(const uint32_t*)(pBl + rb * 80 + co + 16);
#pragma unroll
                for (int mi = 0; mi < 2; mi++) {
                    mma16816(acc[mi][ni], ah[mi], bh);
                    mma16816(acc[mi][ni], al[mi], bh);
                    mma16816(acc[mi][ni], ah[mi], bl);
                }
            }
        }
        __syncthreads();
    }

#pragma unroll
    for (int mi = 0; mi < 2; mi++) {
        int m = m0 + wm * 32 + mi * 16 + g;
#pragma unroll
        for (int ni = 0; ni < 8; ni++) {
            int n = n0 + wn * 64 + ni * 8 + t * 2;
            float bx = __ldg(bias + n), by = __ldg(bias + n + 1);
            float2 v0 = {acc[mi][ni][0] + bx, acc[mi][ni][1] + by};
            float2 v1 = {acc[mi][ni][2] + bx, acc[mi][ni][3] + by};
            *(float2*)(zx + (size_t)m * kG + n) = v0;
            *(float2*)(zx + (size_t)(m + 8) * kG + n) = v1;
        }
    }
}

// ------------------------------ persistent HMMA scan ------------------------
// 128 CTAs: CTA = dir*64 + g owns 8 units (32 gate cols).
// Per step: z[64,32] = h[64,512] @ UrSlice[512,32], bf16 hi/lo 3-pass on HMMA.
// SMEM: Ah[64][520]bf16, Al, Bh[32][520]bf16, Bl, zex[64][33]f32.
#define SA_STRIDE 1040            /* bytes per A/B row: 512*2 + 16 pad */
#define OFF_AL 66560
#define OFF_BH 133120
#define OFF_BL 166400
#define OFF_ZX 199680
#define SCAN_SMEM 208128

__global__ __launch_bounds__(256, 1) void scan_kernel(
    const float* __restrict__ Ur_f, const float* __restrict__ Ur_b,
    const int* __restrict__ enc,
    float* __restrict__ out2, float* __restrict__ h_final,
    float* __restrict__ c_final, int layer2) {
    extern __shared__ char dynsmem[];
    char* pAh = dynsmem;
    char* pAl = dynsmem + OFF_AL;
    char* pBh = dynsmem + OFF_BH;
    char* pBl = dynsmem + OFF_BL;
    float* zex = (float*)(dynsmem + OFF_ZX);

    const int cta = blockIdx.x;
    const int d = cta >> 6;
    const int g = cta & 63;
    const int j0 = g * 8;
    const int tid = threadIdx.x;
    const int w = tid >> 5, lane = tid & 31;
    const int fg = lane >> 2, ft = lane & 3;
    const int m0 = (w & 3) * 16;          // warp M rows
    const int n0 = (w >> 2) * 16;         // warp N cols (two 8-wide tiles)
    const int er = tid >> 2;              // epilogue batch row 0..63
    const int eu = tid & 3;               // epilogue units eu, eu+4

    const float* __restrict__ Ur = d ? Ur_b : Ur_f;
    const float* __restrict__ ew = d ? g_embw1 : g_embw0;
    const float* __restrict__ zx = d ? g_zx1 : g_zx0;
    unsigned int* barp = &g_bar[layer2 * 2 + d];

    // fill B tiles: Bh/Bl[n][k], n = q*8+jj <-> Ur col q*512 + j0 + jj
    for (int i = tid; i < 16384; i += 256) {
        int n = i >> 9, k = i & 511;
        int q = n >> 3, jj = n & 7;
        float v = __ldg(Ur + (size_t)k * kG + q * kU + j0 + jj);
        __nv_bfloat16 hi = __float2bfloat16(v);
        float lo = v - __bfloat162float(hi);
        *(__nv_bfloat16*)(pBh + n * SA_STRIDE + k * 2) = hi;
        *(__nv_bfloat16*)(pBl + n * SA_STRIDE + k * 2) = __float2bfloat16(lo);
    }
    __syncthreads();

    float hp0 = 0.0f, hp1 = 0.0f, cp0 = 0.0f, cp1 = 0.0f;

    for (int s = 0; s < kT; ++s) {
        const int t = d ? (kT - 1 - s) : s;
        const int par = s & 1;
        const uint32_t* __restrict__ hin = g_hc[layer2][d][par];
        uint32_t* __restrict__ hout = g_hc[layer2][d][par ^ 1];

        // prefetch zx + mask for epilogue cells (er, eu) and (er, eu+4)
        const int tok = __ldg(enc + er * kT + t);
        const int msk = tok != 0;
        float zr[2][4];
        if (!layer2) {
#pragma unroll
            for (int q = 0; q < 4; q++) {
                zr[0][q] = __ldg(ew + (size_t)tok * kG + q * kU + j0 + eu);
                zr[1][q] = __ldg(ew + (size_t)tok * kG + q * kU + j0 + eu + 4);
            }
        } else {
            const float* zb = zx + ((size_t)t * kB + er) * kG;
#pragma unroll
            for (int q = 0; q < 4; q++) {
                zr[0][q] = __ldg(zb + q * kU + j0 + eu);
                zr[1][q] = __ldg(zb + q * kU + j0 + eu + 4);
            }
        }

        // stage h (packed hi|lo u32 [64][512]) -> Ah/Al bf16 smem tiles
        for (int i = tid; i < 8192; i += 256) {
            int r = i >> 7, c = i & 127;
            uint4 v = __ldcg((const uint4*)(hin + r * kU + c * 4));
            uint32_t hi01 = __byte_perm(v.x, v.y, 0x5410);
            uint32_t hi23 = __byte_perm(v.z, v.w, 0x5410);
            uint32_t lo01 = __byte_perm(v.x, v.y, 0x7632);
            uint32_t lo23 = __byte_perm(v.z, v.w, 0x7632);
            *(uint2*)(pAh + r * SA_STRIDE + c * 8) = make_uint2(hi01, hi23);
            *(uint2*)(pAl + r * SA_STRIDE + c * 8) = make_uint2(lo01, lo23);
        }
        __syncthreads();

        // HMMA: z[64,32], 3-pass hi/lo (Ah*Bh + Al*Bh + Ah*Bl)
        float acc[2][4] = {{0.f, 0.f, 0.f, 0.f}, {0.f, 0.f, 0.f, 0.f}};
#pragma unroll 4
        for (int kb = 0; kb < 512; kb += 16) {
            const int co = (kb + ft * 2) * 2;
            uint32_t ah[4], al[4];
            ah[0] = *(const uint32_t*)(pAh + (m0 + fg)     * SA_STRIDE + co);
            ah[1] = *(const uint32_t*)(pAh + (m0 + fg + 8) * SA_STRIDE + co);
            ah[2] = *(const uint32_t*)(pAh + (m0 + fg)     * SA_STRIDE + co + 16);
            ah[3] = *(const uint32_t*)(pAh + (m0 + fg + 8) * SA_STRIDE + co + 16);
            al[0] = *(const uint32_t*)(pAl + (m0 + fg)     * SA_STRIDE + co);
            al[1] = *(const uint32_t*)(pAl + (m0 + fg + 8) * SA_STRIDE + co);
            al[2] = *(const uint32_t*)(pAl + (m0 + fg)     * SA_STRIDE + co + 16);
            al[3] = *(const uint32_t*)(pAl + (m0 + fg + 8) * SA_STRIDE + co + 16);
#pragma unroll
            for (int ni = 0; ni < 2; ni++) {
                int rb = n0 + ni * 8 + fg;
                uint32_t bh[2], bl[2];
                bh[0] = *(const uint32_t*)(pBh + rb * SA_STRIDE + co);
                bh[1] = *(const uint32_t*)(pBh + rb * SA_STRIDE + co + 16);
                bl[0] = *(const uint32_t*)(pBl + rb * SA_STRIDE + co);
                bl[1] = *(const uint32_t*)(pBl + rb * SA_STRIDE + co + 16);
                mma16816(acc[ni], ah, bh);
                mma16816(acc[ni], al, bh);
                mma16816(acc[ni], ah, bl);
            }
        }
        // write z to exchange buffer
#pragma unroll
        for (int ni = 0; ni < 2; ni++) {
            int nc = n0 + ni * 8 + ft * 2;
            zex[(m0 + fg)     * 33 + nc]     = acc[ni][0];
            zex[(m0 + fg)     * 33 + nc + 1] = acc[ni][1];
            zex[(m0 + fg + 8) * 33 + nc]     = acc[ni][2];
            zex[(m0 + fg + 8) * 33 + nc + 1] = acc[ni][3];
        }
        __syncthreads();

        // LSTM epilogue: thread owns (er, eu) and (er, eu+4)
#pragma unroll
        for (int uu = 0; uu < 2; ++uu) {
            const int u = eu + uu * 4;
            float zi = zex[er * 33 +      u] + zr[uu][0];
            float zf = zex[er * 33 +  8 + u] + zr[uu][1];
            float zg = zex[er * 33 + 16 + u] + zr[uu][2];
            float zo = zex[er * 33 + 24 + u] + zr[uu][3];
            float ii = sigmoidf_(zi), ff = sigmoidf_(zf);
            float gg = tanhf(zg), oo = sigmoidf_(zo);
            float& hp = uu ? hp1 : hp0;
            float& cp = uu ? cp1 : cp0;
            float cn = ff * cp + ii * gg;
            float hn = oo * tanhf(cn);
            if (!msk) { hn = hp; cn = cp; }
            hp = hn; cp = cn;
            __nv_bfloat16 bhi = __float2bfloat16(hn);
            __nv_bfloat16 blo = __float2bfloat16(hn - __bfloat162float(bhi));
            unsigned short uh = *reinterpret_cast<unsigned short*>(&bhi);
            unsigned short ul = *reinterpret_cast<unsigned short*>(&blo);
            __stcg(&hout[er * kU + j0 + u], (uint32_t)uh | ((uint32_t)ul << 16));
            if (!layer2) {
                size_t idx = ((size_t)t * kB + er) * kF + d * kU + j0 + u;
                g_ah[idx] = bhi;
                g_al[idx] = blo;
            } else {
                out2[((size_t)er * kT + t) * kF + d * kU + j0 + u] = hn;
                if (s == kT - 1) {
                    h_final[er * kF + d * kU + j0 + u] = hn;
                    c_final[er * kF + d * kU + j0 + u] = cn;
                }
            }
        }

        // inter-CTA barrier (per layer+direction group)
        if (s != kT - 1) {
            __threadfence();
            __syncthreads();
            if (tid == 0) {
                unsigned tgt = 64u * (unsigned)(s + 1);
                atomicAdd(barp, 1u);
                unsigned v;
                do {
                    asm volatile("ld.global.cg.u32 %0, [%1];"
                                 : "=r"(v) : "l"(barp) : "memory");
                    if (v < tgt) __nanosleep(64);
                } while (v < tgt);
                __threadfence();
            }
            __syncthreads();
        }
    }
}

// ------------------------------ launch --------------------------------------
extern "C" void kernel_launch(void* const* d_in, const int* in_sizes, int n_in,
                              void* d_out, int out_size) {
    const int*   enc = (const int*)d_in[0];
    const float* emb = (const float*)d_in[1];
    const float* W1f = (const float*)d_in[2];
    const float* U1f = (const float*)d_in[3];
    const float* b1f = (const float*)d_in[4];
    const float* W1b = (const float*)d_in[5];
    const float* U1b = (const float*)d_in[6];
    const float* b1b = (const float*)d_in[7];
    const float* W2f = (const float*)d_in[8];
    const float* U2f = (const float*)d_in[9];
    const float* b2f = (const float*)d_in[10];
    const float* W2b = (const float*)d_in[11];
    const float* U2b = (const float*)d_in[12];
    const float* b2b = (const float*)d_in[13];

    float* out  = (float*)d_out;
    float* out2 = out;                                   // [B,T,2U]
    float* h2   = out + (size_t)kB * kT * kF;
    float* c2   = h2 + (size_t)kB * kF;

    cudaFuncSetAttribute(scan_kernel, cudaFuncAttributeMaxDynamicSharedMemorySize,
                         SCAN_SMEM);
    cudaFuncSetAttribute(mma_gemm_kernel, cudaFuncAttributeMaxDynamicSharedMemorySize,
                         MM_SMEM);

    // embW = emb @ W1 + b1  (V=128 -> gather replaces layer-1 GEMM)
    gemm_f32<<<dim3(16, 1), 256>>>(emb, W1f, b1f, 0, kE);
    gemm_f32<<<dim3(16, 1), 256>>>(emb, W1b, b1b, 1, kE);

    // W2 transpose + bf16 hi/lo split
    wsplit_kernel<<<dim3(64, 32, 2), 256>>>(W2f, W2b);

    // zero h buffers (both layers) + barrier counters, once
    init_kernel<<<128, 256>>>();

    // layer-1 scan (HMMA recurrent GEMM; emits bf16 hi/lo A operand)
    scan_kernel<<<128, 256, SCAN_SMEM>>>(U1f, U1b, enc,
                                         nullptr, nullptr, nullptr, 0);

    // layer-2 input projection: warp-mma bf16, 3-pass split, cp.async pipeline
    mma_gemm_kernel<<<dim3(16, 128, 2), 256, MM_SMEM>>>(b2f, b2b);

    // layer-2 scan -> outputs
    scan_kernel<<<128, 256, SCAN_SMEM>>>(U2f, U2b, enc,
                                         out2, h2, c2, 1);
}

// round 10
// speedup vs baseline: 2.0046x; 1.0026x over previous
#include <cuda_runtime.h>
#include <cuda_bf16.h>
#include <cstdint>

// ---------------------------------------------------------------------------
// StackedBidirectionalLSTMEncoder  (B=64, T=256, V=128, E=512, U=512)
// Round 9: recurrent scans moved to warp-mma bf16 (hi/lo 3-pass), reusing the
// fragment mapping validated by the passing mma_gemm_kernel.
//   embW = emb@W1+b1 (gather replaces layer-1 GEMM)
//   scan: persistent 128 CTAs, per-step h[64,512]@Ur[512,2048] on HMMA
//   layer-2 GEMM via warp-mma bf16 (unchanged, validated)
// ---------------------------------------------------------------------------

#define kB 64
#define kT 256
#define kE 512
#define kU 512
#define kG 2048   /* 4U */
#define kF 1024   /* 2U */

// ------------------------------ scratch ------------------------------------
__device__ float g_zx0[33554432];                   // [t*B+b][2048] fwd (layer2)
__device__ float g_zx1[33554432];                   // bwd
__device__ __nv_bfloat16 g_ah[16777216];            // A hi  [16384][1024]
__device__ __nv_bfloat16 g_al[16777216];            // A lo
__device__ __nv_bfloat16 g_bh0[2097152];            // W2f^T hi [2048][1024]
__device__ __nv_bfloat16 g_bl0[2097152];
__device__ __nv_bfloat16 g_bh1[2097152];            // W2b^T hi
__device__ __nv_bfloat16 g_bl1[2097152];
__device__ float g_embw0[262144];                   // emb@W1f+b1f [128][2048]
__device__ float g_embw1[262144];
__device__ uint32_t g_hc[2][2][2][kB * kU];         // [layer][dir][par] hi|lo<<16
__device__ unsigned int g_bar[4];                   // [layer*2+dir]

// ------------------------------ f32x2 helpers ------------------------------
__device__ __forceinline__ unsigned long long pk2(float lo, float hi) {
    unsigned long long r;
    asm("mov.b64 %0, {%1, %2};" : "=l"(r) : "f"(lo), "f"(hi));
    return r;
}
__device__ __forceinline__ void upk2(unsigned long long v, float& lo, float& hi) {
    asm("mov.b64 {%0, %1}, %2;" : "=f"(lo), "=f"(hi) : "l"(v));
}
__device__ __forceinline__ unsigned long long ffma2(unsigned long long a,
                                                    unsigned long long b,
                                                    unsigned long long c) {
    unsigned long long d;
    asm("fma.rn.f32x2 %0, %1, %2, %3;" : "=l"(d) : "l"(a), "l"(b), "l"(c));
    return d;
}
__device__ __forceinline__ float sigmoidf_(float x) {
    return 1.0f / (1.0f + __expf(-x));
}

// ------------------------------ cp.async helpers ----------------------------
__device__ __forceinline__ uint32_t smem_u32(const void* p) {
    uint32_t a;
    asm("{ .reg .u64 t; cvta.to.shared.u64 t, %1; cvt.u32.u64 %0, t; }"
        : "=r"(a) : "l"(p));
    return a;
}
__device__ __forceinline__ void cp16(uint32_t d, const void* s) {
    asm volatile("cp.async.cg.shared.global [%0], [%1], 16;" :: "r"(d), "l"(s));
}
__device__ __forceinline__ void cp_commit() { asm volatile("cp.async.commit_group;" ::: "memory"); }
__device__ __forceinline__ void cp_wait1()  { asm volatile("cp.async.wait_group 1;" ::: "memory"); }
__device__ __forceinline__ void cp_wait0()  { asm volatile("cp.async.wait_group 0;" ::: "memory"); }

// bf16 warp mma: D(16x8,f32) += A(16x16 row) * B(16x8 col)
__device__ __forceinline__ void mma16816(float* c, const uint32_t* a,
                                         const uint32_t* b) {
    asm volatile(
        "mma.sync.aligned.m16n8k16.row.col.f32.bf16.bf16.f32 "
        "{%0,%1,%2,%3}, {%4,%5,%6,%7}, {%8,%9}, {%0,%1,%2,%3};"
        : "+f"(c[0]), "+f"(c[1]), "+f"(c[2]), "+f"(c[3])
        : "r"(a[0]), "r"(a[1]), "r"(a[2]), "r"(a[3]), "r"(b[0]), "r"(b[1]));
}

// ------------------------------ init ----------------------------------------
__global__ void init_kernel() {
    int i = blockIdx.x * blockDim.x + threadIdx.x;
    if (i < 4) g_bar[i] = 0u;
    uint32_t* h = (uint32_t*)g_hc;
    for (int j = i; j < 2 * 2 * 2 * kB * kU; j += gridDim.x * blockDim.x) h[j] = 0u;
}

// ------------------------------ fp32 GEMM (embW only; M=128) ---------------
// C selected IN DEVICE CODE — never pass __device__ symbols from host.
__global__ __launch_bounds__(256, 2) void gemm_f32(
    const float* __restrict__ A, const float* __restrict__ W,
    const float* __restrict__ bias, int c_sel, int K) {
    float* __restrict__ C = c_sel ? g_embw1 : g_embw0;
    __shared__ float As[16][136];
    __shared__ float Bs[16][128];
    const int tid = threadIdx.x;
    const int tx = tid & 15;
    const int ty = tid >> 4;
    const int m0 = blockIdx.y * 128;
    const int n0 = blockIdx.x * 128;

    unsigned long long acc[8][4];
#pragma unroll
    for (int i = 0; i < 8; i++)
#pragma unroll
        for (int j = 0; j < 4; j++) acc[i][j] = pk2(0.0f, 0.0f);

    for (int k0 = 0; k0 < K; k0 += 16) {
#pragma unroll
        for (int l = 0; l < 2; ++l) {
            int f = tid + l * 256;
            int m = f >> 2, kc = (f & 3) * 4;
            float4 v = *(const float4*)(A + (size_t)(m0 + m) * K + k0 + kc);
            As[kc + 0][m] = v.x; As[kc + 1][m] = v.y;
            As[kc + 2][m] = v.z; As[kc + 3][m] = v.w;
            int kr = f >> 5, nc = (f & 31) * 4;
            *(float4*)&Bs[kr][nc] =
                *(const float4*)(W + (size_t)(k0 + kr) * kG + n0 + nc);
        }
        __syncthreads();
#pragma unroll
        for (int k = 0; k < 16; ++k) {
            float4 a0 = *(const float4*)&As[k][ty * 8];
            float4 a1 = *(const float4*)&As[k][ty * 8 + 4];
            float4 b0 = *(const float4*)&Bs[k][tx * 8];
            float4 b1 = *(const float4*)&Bs[k][tx * 8 + 4];
            unsigned long long bp[4] = {pk2(b0.x, b0.y), pk2(b0.z, b0.w),
                                        pk2(b1.x, b1.y), pk2(b1.z, b1.w)};
            float av[8] = {a0.x, a0.y, a0.z, a0.w, a1.x, a1.y, a1.z, a1.w};
#pragma unroll
            for (int i = 0; i < 8; i++) {
                unsigned long long ad = pk2(av[i], av[i]);
#pragma unroll
                for (int j = 0; j < 4; j++) acc[i][j] = ffma2(ad, bp[j], acc[i][j]);
            }
        }
        __syncthreads();
    }
#pragma unroll
    for (int i = 0; i < 8; i++) {
        int m = m0 + ty * 8 + i;
#pragma unroll
        for (int jh = 0; jh < 2; jh++) {
            float l0, h0, l1, h1;
            upk2(acc[i][jh * 2 + 0], l0, h0);
            upk2(acc[i][jh * 2 + 1], l1, h1);
            int n = n0 + tx * 8 + jh * 4;
            float4 v;
            v.x = l0 + bias[n + 0];
            v.y = h0 + bias[n + 1];
            v.z = l1 + bias[n + 2];
            v.w = h1 + bias[n + 3];
            *(float4*)(C + (size_t)m * kG + n) = v;
        }
    }
}

// ------------------------------ W2 transpose + bf16 split -------------------
__global__ void wsplit_kernel(const float* __restrict__ W2f,
                              const float* __restrict__ W2b) {
    __shared__ float s[32][33];
    const int d = blockIdx.z;
    const float* __restrict__ W = d ? W2b : W2f;
    __nv_bfloat16* __restrict__ Bh = d ? g_bh1 : g_bh0;
    __nv_bfloat16* __restrict__ Bl = d ? g_bl1 : g_bl0;
    const int n0 = blockIdx.x * 32, k0 = blockIdx.y * 32;
    const int tx = threadIdx.x & 31, ty = threadIdx.x >> 5;
#pragma unroll
    for (int i = 0; i < 4; ++i) {
        int k = ty + i * 8;
        s[k][tx] = W[(size_t)(k0 + k) * kG + n0 + tx];
    }
    __syncthreads();
#pragma unroll
    for (int i = 0; i < 4; ++i) {
        int r = ty + i * 8;
        float v = s[tx][r];
        __nv_bfloat16 hi = __float2bfloat16(v);
        float lo = v - __bfloat162float(hi);
        size_t o = (size_t)(n0 + r) * 1024 + k0 + tx;
        Bh[o] = hi;
        Bl[o] = __float2bfloat16(lo);
    }
}

// ------------------------------ warp-mma layer-2 GEMM (validated) ----------
#define TILE_B   10240
#define STAGE_B  (4 * TILE_B)
#define MM_SMEM  (3 * STAGE_B)

__global__ __launch_bounds__(256, 1) void mma_gemm_kernel(
    const float* __restrict__ bias_f, const float* __restrict__ bias_b) {
    extern __shared__ char dynsmem[];
    const int tid = threadIdx.x;
    const int wid = tid >> 5, lane = tid & 31;
    const int g = lane >> 2, t = lane & 3;
    const int wm = wid & 3, wn = wid >> 2;
    const int d = blockIdx.z;
    const int n0 = blockIdx.x * 128;
    const int m0 = blockIdx.y * 128;
    const __nv_bfloat16* __restrict__ Bh = d ? g_bh1 : g_bh0;
    const __nv_bfloat16* __restrict__ Bl = d ? g_bl1 : g_bl0;
    const float* __restrict__ bias = d ? bias_b : bias_f;
    float* __restrict__ zx = d ? g_zx1 : g_zx0;

    const uint32_t sb32 = smem_u32(dynsmem);

    float acc[2][8][4];
#pragma unroll
    for (int mi = 0; mi < 2; mi++)
#pragma unroll
        for (int ni = 0; ni < 8; ni++)
#pragma unroll
            for (int v = 0; v < 4; v++) acc[mi][ni][v] = 0.0f;

    auto load_chunk = [&](int s, int kc) {
        const uint32_t base = sb32 + (uint32_t)s * STAGE_B;
        const int k0 = kc * 32;
        for (int idx = tid; idx < 2048; idx += 256) {
            int tile = idx >> 9;
            int r = (idx >> 2) & 127;
            int c = idx & 3;
            const __nv_bfloat16* src;
            if (tile < 2) src = (tile == 0 ? g_ah : g_al) + (size_t)(m0 + r) * 1024 + k0 + c * 8;
            else          src = (tile == 2 ? Bh : Bl)     + (size_t)(n0 + r) * 1024 + k0 + c * 8;
            cp16(base + tile * TILE_B + r * 80 + c * 16, src);
        }
        cp_commit();
    };

    load_chunk(0, 0);
    load_chunk(1, 1);

    for (int c = 0; c < 32; ++c) {
        if (c + 1 < 32) cp_wait1(); else cp_wait0();
        __syncthreads();
        if (c + 2 < 32) load_chunk((c + 2) % 3, c + 2);

        const char* stg = dynsmem + (size_t)(c % 3) * STAGE_B;
        const char* pAh = stg;
        const char* pAl = stg + TILE_B;
        const char* pBh = stg + 2 * TILE_B;
        const char* pBl = stg + 3 * TILE_B;

#pragma unroll
        for (int ks = 0; ks < 2; ++ks) {
            const int kb = ks * 16;
            uint32_t ah[2][4], al[2][4];
#pragma unroll
            for (int mi = 0; mi < 2; mi++) {
                int ra = wm * 32 + mi * 16 + g;
                int co = (kb + t * 2) * 2;
                ah[mi][0] = *(const uint32_t*)(pAh + (ra)     * 80 + co);
                ah[mi][1] = *(const uint32_t*)(pAh + (ra + 8) * 80 + co);
                ah[mi][2] = *(const uint32_t*)(pAh + (ra)     * 80 + co + 16);
                ah[mi][3] = *(const uint32_t*)(pAh + (ra + 8) * 80 + co + 16);
                al[mi][0] = *(const uint32_t*)(pAl + (ra)     * 80 + co);
                al[mi][1] = *(const uint32_t*)(pAl + (ra + 8) * 80 + co);
                al[mi][2] = *(const uint32_t*)(pAl + (ra)     * 80 + co + 16);
                al[mi][3] = *(const uint32_t*)(pAl + (ra + 8) * 80 + co + 16);
            }
#pragma unroll
            for (int ni = 0; ni < 8; ni++) {
                int rb = wn * 64 + ni * 8 + g;
                int co = (kb + t * 2) * 2;
                uint32_t bh[2], bl[2];
                bh[0] = *(const uint32_t*)(pBh + rb * 80 + co);
                bh[1] = *(const uint32_t*)(pBh + rb * 80 + co + 16);
                bl[0] = *(const uint32_t*)(pBl + rb * 80 + co);
                bl[1] = *(const uint32_t*)(pBl + rb * 80 + co + 16);
#pragma unroll
                for (int mi = 0; mi < 2; mi++) {
                    mma16816(acc[mi][ni], ah[mi], bh);
                    mma16816(acc[mi][ni], al[mi], bh);
                    mma16816(acc[mi][ni], ah[mi], bl);
                }
            }
        }
        __syncthreads();
    }

#pragma unroll
    for (int mi = 0; mi < 2; mi++) {
        int m = m0 + wm * 32 + mi * 16 + g;
#pragma unroll
        for (int ni = 0; ni < 8; ni++) {
            int n = n0 + wn * 64 + ni * 8 + t * 2;
            float bx = __ldg(bias + n), by = __ldg(bias + n + 1);
            float2 v0 = {acc[mi][ni][0] + bx, acc[mi][ni][1] + by};
            float2 v1 = {acc[mi][ni][2] + bx, acc[mi][ni][3] + by};
            *(float2*)(zx + (size_t)m * kG + n) = v0;
            *(float2*)(zx + (size_t)(m + 8) * kG + n) = v1;
        }
    }
}

// ------------------------------ persistent HMMA scan ------------------------
// 128 CTAs: CTA = dir*64 + g owns 8 units (32 gate cols).
// Per step: z[64,32] = h[64,512] @ UrSlice[512,32], bf16 hi/lo 3-pass on HMMA.
// SMEM: Ah[64][520]bf16, Al, Bh[32][520]bf16, Bl, zex[64][33]f32.
#define SA_STRIDE 1040            /* bytes per A/B row: 512*2 + 16 pad */
#define OFF_AL 66560
#define OFF_BH 133120
#define OFF_BL 166400
#define OFF_ZX 199680
#define SCAN_SMEM 208128

__global__ __launch_bounds__(256, 1) void scan_kernel(
    const float* __restrict__ Ur_f, const float* __restrict__ Ur_b,
    const int* __restrict__ enc,
    float* __restrict__ out2, float* __restrict__ h_final,
    float* __restrict__ c_final, int layer2) {
    extern __shared__ char dynsmem[];
    char* pAh = dynsmem;
    char* pAl = dynsmem + OFF_AL;
    char* pBh = dynsmem + OFF_BH;
    char* pBl = dynsmem + OFF_BL;
    float* zex = (float*)(dynsmem + OFF_ZX);

    const int cta = blockIdx.x;
    const int d = cta >> 6;
    const int g = cta & 63;
    const int j0 = g * 8;
    const int tid = threadIdx.x;
    const int w = tid >> 5, lane = tid & 31;
    const int fg = lane >> 2, ft = lane & 3;
    const int m0 = (w & 3) * 16;          // warp M rows
    const int n0 = (w >> 2) * 16;         // warp N cols (two 8-wide tiles)
    const int er = tid >> 2;              // epilogue batch row 0..63
    const int eu = tid & 3;               // epilogue units eu, eu+4

    const float* __restrict__ Ur = d ? Ur_b : Ur_f;
    const float* __restrict__ ew = d ? g_embw1 : g_embw0;
    const float* __restrict__ zx = d ? g_zx1 : g_zx0;
    unsigned int* barp = &g_bar[layer2 * 2 + d];

    // fill B tiles: Bh/Bl[n][k], n = q*8+jj <-> Ur col q*512 + j0 + jj
    for (int i = tid; i < 16384; i += 256) {
        int n = i >> 9, k = i & 511;
        int q = n >> 3, jj = n & 7;
        float v = __ldg(Ur + (size_t)k * kG + q * kU + j0 + jj);
        __nv_bfloat16 hi = __float2bfloat16(v);
        float lo = v - __bfloat162float(hi);
        *(__nv_bfloat16*)(pBh + n * SA_STRIDE + k * 2) = hi;
        *(__nv_bfloat16*)(pBl + n * SA_STRIDE + k * 2) = __float2bfloat16(lo);
    }
    __syncthreads();

    float hp0 = 0.0f, hp1 = 0.0f, cp0 = 0.0f, cp1 = 0.0f;

    for (int s = 0; s < kT; ++s) {
        const int t = d ? (kT - 1 - s) : s;
        const int par = s & 1;
        const uint32_t* __restrict__ hin = g_hc[layer2][d][par];
        uint32_t* __restrict__ hout = g_hc[layer2][d][par ^ 1];

        // prefetch zx + mask for epilogue cells (er, eu) and (er, eu+4)
        const int tok = __ldg(enc + er * kT + t);
        const int msk = tok != 0;
        float zr[2][4];
        if (!layer2) {
#pragma unroll
            for (int q = 0; q < 4; q++) {
                zr[0][q] = __ldg(ew + (size_t)tok * kG + q * kU + j0 + eu);
                zr[1][q] = __ldg(ew + (size_t)tok * kG + q * kU + j0 + eu + 4);
            }
        } else {
            const float* zb = zx + ((size_t)t * kB + er) * kG;
#pragma unroll
            for (int q = 0; q < 4; q++) {
                zr[0][q] = __ldg(zb + q * kU + j0 + eu);
                zr[1][q] = __ldg(zb + q * kU + j0 + eu + 4);
            }
        }

        // stage h (packed hi|lo u32 [64][512]) -> Ah/Al bf16 smem tiles
        for (int i = tid; i < 8192; i += 256) {
            int r = i >> 7, c = i & 127;
            uint4 v = __ldcg((const uint4*)(hin + r * kU + c * 4));
            uint32_t hi01 = __byte_perm(v.x, v.y, 0x5410);
            uint32_t hi23 = __byte_perm(v.z, v.w, 0x5410);
            uint32_t lo01 = __byte_perm(v.x, v.y, 0x7632);
            uint32_t lo23 = __byte_perm(v.z, v.w, 0x7632);
            *(uint2*)(pAh + r * SA_STRIDE + c * 8) = make_uint2(hi01, hi23);
            *(uint2*)(pAl + r * SA_STRIDE + c * 8) = make_uint2(lo01, lo23);
        }
        __syncthreads();

        // HMMA: z[64,32], 3-pass hi/lo (Ah*Bh + Al*Bh + Ah*Bl)
        float acc[2][4] = {{0.f, 0.f, 0.f, 0.f}, {0.f, 0.f, 0.f, 0.f}};
#pragma unroll 4
        for (int kb = 0; kb < 512; kb += 16) {
            const int co = (kb + ft * 2) * 2;
            uint32_t ah[4], al[4];
            ah[0] = *(const uint32_t*)(pAh + (m0 + fg)     * SA_STRIDE + co);
            ah[1] = *(const uint32_t*)(pAh + (m0 + fg + 8) * SA_STRIDE + co);
            ah[2] = *(const uint32_t*)(pAh + (m0 + fg)     * SA_STRIDE + co + 16);
            ah[3] = *(const uint32_t*)(pAh + (m0 + fg + 8) * SA_STRIDE + co + 16);
            al[0] = *(const uint32_t*)(pAl + (m0 + fg)     * SA_STRIDE + co);
            al[1] = *(const uint32_t*)(pAl + (m0 + fg + 8) * SA_STRIDE + co);
            al[2] = *(const uint32_t*)(pAl + (m0 + fg)     * SA_STRIDE + co + 16);
            al[3] = *(const uint32_t*)(pAl + (m0 + fg + 8) * SA_STRIDE + co + 16);
#pragma unroll
            for (int ni = 0; ni < 2; ni++) {
                int rb = n0 + ni * 8 + fg;
                uint32_t bh[2], bl[2];
                bh[0] = *(const uint32_t*)(pBh + rb * SA_STRIDE + co);
                bh[1] = *(const uint32_t*)(pBh + rb * SA_STRIDE + co + 16);
                bl[0] = *(const uint32_t*)(pBl + rb * SA_STRIDE + co);
                bl[1] = *(const uint32_t*)(pBl + rb * SA_STRIDE + co + 16);
                mma16816(acc[ni], ah, bh);
                mma16816(acc[ni], al, bh);
                mma16816(acc[ni], ah, bl);
            }
        }
        // write z to exchange buffer
#pragma unroll
        for (int ni = 0; ni < 2; ni++) {
            int nc = n0 + ni * 8 + ft * 2;
            zex[(m0 + fg)     * 33 + nc]     = acc[ni][0];
            zex[(m0 + fg)     * 33 + nc + 1] = acc[ni][1];
            zex[(m0 + fg + 8) * 33 + nc]     = acc[ni][2];
            zex[(m0 + fg + 8) * 33 + nc + 1] = acc[ni][3];
        }
        __syncthreads();

        // LSTM epilogue: thread owns (er, eu) and (er, eu+4)
#pragma unroll
        for (int uu = 0; uu < 2; ++uu) {
            const int u = eu + uu * 4;
            float zi = zex[er * 33 +      u] + zr[uu][0];
            float zf = zex[er * 33 +  8 + u] + zr[uu][1];
            float zg = zex[er * 33 + 16 + u] + zr[uu][2];
            float zo = zex[er * 33 + 24 + u] + zr[uu][3];
            float ii = sigmoidf_(zi), ff = sigmoidf_(zf);
            float gg = tanhf(zg), oo = sigmoidf_(zo);
            float& hp = uu ? hp1 : hp0;
            float& cp = uu ? cp1 : cp0;
            float cn = ff * cp + ii * gg;
            float hn = oo * tanhf(cn);
            if (!msk) { hn = hp; cn = cp; }
            hp = hn; cp = cn;
            __nv_bfloat16 bhi = __float2bfloat16(hn);
            __nv_bfloat16 blo = __float2bfloat16(hn - __bfloat162float(bhi));
            unsigned short uh = *reinterpret_cast<unsigned short*>(&bhi);
            unsigned short ul = *reinterpret_cast<unsigned short*>(&blo);
            __stcg(&hout[er * kU + j0 + u], (uint32_t)uh | ((uint32_t)ul << 16));
            if (!layer2) {
                size_t idx = ((size_t)t * kB + er) * kF + d * kU + j0 + u;
                g_ah[idx] = bhi;
                g_al[idx] = blo;
            } else {
                out2[((size_t)er * kT + t) * kF + d * kU + j0 + u] = hn;
                if (s == kT - 1) {
                    h_final[er * kF + d * kU + j0 + u] = hn;
                    c_final[er * kF + d * kU + j0 + u] = cn;
                }
            }
        }

        // inter-CTA barrier (per layer+direction group)
        if (s != kT - 1) {
            __threadfence();
            __syncthreads();
            if (tid == 0) {
                unsigned tgt = 64u * (unsigned)(s + 1);
                atomicAdd(barp, 1u);
                unsigned v;
                do {
                    asm volatile("ld.global.cg.u32 %0, [%1];"
                                 : "=r"(v) : "l"(barp) : "memory");
                    if (v < tgt) __nanosleep(64);
                } while (v < tgt);
                __threadfence();
            }
            __syncthreads();
        }
    }
}

// ------------------------------ launch --------------------------------------
extern "C" void kernel_launch(void* const* d_in, const int* in_sizes, int n_in,
                              void* d_out, int out_size) {
    const int*   enc = (const int*)d_in[0];
    const float* emb = (const float*)d_in[1];
    const float* W1f = (const float*)d_in[2];
    const float* U1f = (const float*)d_in[3];
    const float* b1f = (const float*)d_in[4];
    const float* W1b = (const float*)d_in[5];
    const float* U1b = (const float*)d_in[6];
    const float* b1b = (const float*)d_in[7];
    const float* W2f = (const float*)d_in[8];
    const float* U2f = (const float*)d_in[9];
    const float* b2f = (const float*)d_in[10];
    const float* W2b = (const float*)d_in[11];
    const float* U2b = (const float*)d_in[12];
    const float* b2b = (const float*)d_in[13];

    float* out  = (float*)d_out;
    float* out2 = out;                                   // [B,T,2U]
    float* h2   = out + (size_t)kB * kT * kF;
    float* c2   = h2 + (size_t)kB * kF;

    cudaFuncSetAttribute(scan_kernel, cudaFuncAttributeMaxDynamicSharedMemorySize,
                         SCAN_SMEM);
    cudaFuncSetAttribute(mma_gemm_kernel, cudaFuncAttributeMaxDynamicSharedMemorySize,
                         MM_SMEM);

    // embW = emb @ W1 + b1  (V=128 -> gather replaces layer-1 GEMM)
    gemm_f32<<<dim3(16, 1), 256>>>(emb, W1f, b1f, 0, kE);
    gemm_f32<<<dim3(16, 1), 256>>>(emb, W1b, b1b, 1, kE);

    // W2 transpose + bf16 hi/lo split
    wsplit_kernel<<<dim3(64, 32, 2), 256>>>(W2f, W2b);

    // zero h buffers (both layers) + barrier counters, once
    init_kernel<<<128, 256>>>();

    // layer-1 scan (HMMA recurrent GEMM; emits bf16 hi/lo A operand)
    scan_kernel<<<128, 256, SCAN_SMEM>>>(U1f, U1b, enc,
                                         nullptr, nullptr, nullptr, 0);

    // layer-2 input projection: warp-mma bf16, 3-pass split, cp.async pipeline
    mma_gemm_kernel<<<dim3(16, 128, 2), 256, MM_SMEM>>>(b2f, b2b);

    // layer-2 scan -> outputs
    scan_kernel<<<128, 256, SCAN_SMEM>>>(U2f, U2b, enc,
                                         out2, h2, c2, 1);
}